// round 7
// baseline (speedup 1.0000x reference)
#include <cuda_runtime.h>
#include <cuda_bf16.h>

// Problem constants: B=2, H=1, LQ=LK=512, D=64, HID=128
#define NB   2
#define L    512
#define DD   64
#define HID  128

typedef unsigned long long ull;

// Packed f32x2 helpers (sm_103a). NOTE: no packed max in PTX — relu is scalar.
__device__ __forceinline__ ull f2add(ull a, ull b) {
    ull r; asm("add.rn.f32x2 %0, %1, %2;" : "=l"(r) : "l"(a), "l"(b)); return r;
}
__device__ __forceinline__ ull f2fma(ull a, ull b, ull c) {
    ull r; asm("fma.rn.f32x2 %0, %1, %2, %3;" : "=l"(r) : "l"(a), "l"(b), "l"(c)); return r;
}
__device__ __forceinline__ float2 upk(ull v) {
    float2 r; asm("mov.b64 {%0, %1}, %2;" : "=f"(r.x), "=f"(r.y) : "l"(v)); return r;
}
__device__ __forceinline__ ull pk(float x, float y) {
    ull r; asm("mov.b64 %0, {%1, %2};" : "=l"(r) : "f"(x), "f"(y)); return r;
}
// relu on a packed pair: unpack, 2x FMNMX, repack (ptxas pairs the registers)
__device__ __forceinline__ ull f2relu(ull a) {
    float2 t = upk(a);
    return pk(fmaxf(t.x, 0.f), fmaxf(t.y, 0.f));
}

// Scratch (allocation-free rule: __device__ globals)
__device__ float  g_vp[NB * L * DD];             // projected V
__device__ float  g_qaqb[NB * L * HID * 2];      // interleaved (qa, qb) per (row, h)
__device__ float2 g_kbkaT[NB * HID * L];         // TRANSPOSED: [b][h][j] -> (kb+b1, ka+b1)

// ---------------------------------------------------------------------------
// Kernel A: projections + pairwise-MLP feature precompute. (unchanged)
// ---------------------------------------------------------------------------
__global__ __launch_bounds__(256) void prep_kernel(
    const float* __restrict__ q, const float* __restrict__ k,
    const float* __restrict__ v, const float* __restrict__ Ww,
    const float* __restrict__ wb, const float* __restrict__ W1,
    const float* __restrict__ b1)
{
    __shared__ float q_s[4][DD], k_s[4][DD], v_s[4][DD];
    __shared__ float qp_s[4][DD], kp_s[4][DD];

    const int tid  = threadIdx.x;
    const int b    = blockIdx.x >> 7;
    const int r0   = (blockIdx.x & 127) * 4;
    const int base = (b * L + r0) * DD;

    {
        int r = tid >> 6, e = tid & 63;
        q_s[r][e] = q[base + tid];
        k_s[r][e] = k[base + tid];
        v_s[r][e] = v[base + tid];
    }
    __syncthreads();

    {
        int pj = tid >> 6, d = tid & 63;
        if (pj < 3) {
            const float (*src)[DD] = (pj == 0) ? q_s : (pj == 1) ? k_s : v_s;
            float acc[4];
            float bias = wb[d];
            #pragma unroll
            for (int r = 0; r < 4; r++) acc[r] = bias;
            #pragma unroll 8
            for (int e = 0; e < DD; e++) {
                float w = Ww[e * DD + d];
                #pragma unroll
                for (int r = 0; r < 4; r++) acc[r] += src[r][e] * w;
            }
            #pragma unroll
            for (int r = 0; r < 4; r++) {
                if (pj == 0)      qp_s[r][d] = acc[r];
                else if (pj == 1) kp_s[r][d] = acc[r];
                else              g_vp[base + r * DD + d] = acc[r];
            }
        }
    }
    __syncthreads();

    {
        int half = tid >> 7;
        int h    = tid & 127;
        const float (*src)[DD] = half ? kp_s : qp_s;
        float accA[4] = {0.f, 0.f, 0.f, 0.f};
        float accB[4] = {0.f, 0.f, 0.f, 0.f};
        #pragma unroll 8
        for (int e = 0; e < DD; e++) {
            float w1q = W1[e * HID + h];
            float w1k = W1[(DD + e) * HID + h];
            #pragma unroll
            for (int r = 0; r < 4; r++) {
                float x = src[r][e];
                accA[r] += x * w1q;
                accB[r] += x * w1k;
            }
        }
        float bb = b1[h];
        #pragma unroll
        for (int r = 0; r < 4; r++) {
            if (!half) {
                int off = ((b * L + r0 + r) * HID + h) * 2;
                g_qaqb[off + 0] = accA[r];
                g_qaqb[off + 1] = accB[r];
            } else {
                g_kbkaT[(b * HID + h) * L + (r0 + r)] =
                    make_float2(accB[r] + bb, accA[r] + bb);
            }
        }
    }
}

// ---------------------------------------------------------------------------
// Kernel B: grid = NB*(L/2) = 512 blocks, 256 threads = 8 warps.
// Block covers 2 i-rows. Warp jq scores BOTH rows against j-slice
// [jq*64, jq*64+64); lane owns one j-pair. One LDG.128 of kk per h feeds
// 4 (row,j) score-pairs; packed f32x2 add/fma, scalar relu.
// ---------------------------------------------------------------------------
__global__ __launch_bounds__(256, 3) void attn_kernel(
    const float* __restrict__ mask, const float* __restrict__ Wd,
    const float* __restrict__ db,   const float* __restrict__ W2,
    const float* __restrict__ b2,   float* __restrict__ out)
{
    __shared__ ulonglong2 qq_u[HID];     // (qa0,qb0 | qa1,qb1) packed per h
    __shared__ ull        w2_u[HID];     // (w2, w2) per h
    __shared__ float      attn_s[2][L];
    __shared__ float      red_m[2][8], red_s[2][8];
    __shared__ float      o_part[2][8][DD];

    const int tid   = threadIdx.x;
    const int warp  = tid >> 5;
    const int lane  = tid & 31;
    const int jq    = warp;              // j-slice owner
    const int b     = blockIdx.x >> 8;   // / 256
    const int itile = blockIdx.x & 255;
    const int row0  = b * L + itile * 2;

    // Stage packed q-features + duplicated W2
    if (tid < HID) {
        const float2* q0 = (const float2*)(g_qaqb + (size_t)row0 * (HID * 2));
        float2 a0 = q0[tid];
        float2 a1 = q0[HID + tid];
        float4 v4 = make_float4(a0.x, a0.y, a1.x, a1.y);
        qq_u[tid] = *reinterpret_cast<ulonglong2*>(&v4);
    } else {
        int h = tid - HID;
        float w = W2[h];
        float2 wd = make_float2(w, w);
        w2_u[h] = *reinterpret_cast<ull*>(&wd);
    }
    __syncthreads();

    // ---- scores
    // ulonglong2 = 16 B = 2 float2 entries; one h-row of kbkaT = L float2 = L/2 u2.
    const ulonglong2* ktu = reinterpret_cast<const ulonglong2*>(
        g_kbkaT + (size_t)(b * HID) * L) + jq * 32 + lane;

    ull acc00 = 0, acc01 = 0, acc10 = 0, acc11 = 0;  // [row][j parity]

    #pragma unroll 4
    for (int h = 0; h < HID; h++) {
        ulonglong2 kk = __ldg(ktu + h * (L / 2));   // (kb,ka) for j0 | j1  (stride fixed)
        ulonglong2 qv = qq_u[h];                    // row0 pack | row1 pack
        ull        wd = w2_u[h];
        acc00 = f2fma(f2relu(f2add(qv.x, kk.x)), wd, acc00);
        acc01 = f2fma(f2relu(f2add(qv.x, kk.y)), wd, acc01);
        acc10 = f2fma(f2relu(f2add(qv.y, kk.x)), wd, acc10);
        acc11 = f2fma(f2relu(f2add(qv.y, kk.y)), wd, acc11);
    }

    const float b2v2 = 2.f * b2[0];
    float s[2][2];
    {
        float2 a;
        a = upk(acc00); s[0][0] = a.x + a.y;
        a = upk(acc01); s[0][1] = a.x + a.y;
        a = upk(acc10); s[1][0] = a.x + a.y;
        a = upk(acc11); s[1][1] = a.x + a.y;
        const float2* m0 = (const float2*)(mask + (size_t)row0 * L) + jq * 32 + lane;
        float2 mm0 = __ldg(m0);
        float2 mm1 = __ldg(m0 + L / 2);
        s[0][0] += b2v2 + mm0.x * (-1e9f);
        s[0][1] += b2v2 + mm0.y * (-1e9f);
        s[1][0] += b2v2 + mm1.x * (-1e9f);
        s[1][1] += b2v2 + mm1.y * (-1e9f);
    }

    // ---- softmax across the 8 warps (per row)
    float m0 = fmaxf(s[0][0], s[0][1]);
    float m1 = fmaxf(s[1][0], s[1][1]);
    #pragma unroll
    for (int o = 16; o > 0; o >>= 1) {
        m0 = fmaxf(m0, __shfl_xor_sync(0xffffffffu, m0, o));
        m1 = fmaxf(m1, __shfl_xor_sync(0xffffffffu, m1, o));
    }
    if (lane == 0) { red_m[0][jq] = m0; red_m[1][jq] = m1; }
    __syncthreads();
    {
        float g0 = red_m[0][0], g1 = red_m[1][0];
        #pragma unroll
        for (int w = 1; w < 8; w++) { g0 = fmaxf(g0, red_m[0][w]); g1 = fmaxf(g1, red_m[1][w]); }
        m0 = g0; m1 = g1;
    }

    float sum0, sum1;
    s[0][0] = __expf(s[0][0] - m0);
    s[0][1] = __expf(s[0][1] - m0);
    s[1][0] = __expf(s[1][0] - m1);
    s[1][1] = __expf(s[1][1] - m1);
    sum0 = s[0][0] + s[0][1];
    sum1 = s[1][0] + s[1][1];
    #pragma unroll
    for (int o = 16; o > 0; o >>= 1) {
        sum0 += __shfl_xor_sync(0xffffffffu, sum0, o);
        sum1 += __shfl_xor_sync(0xffffffffu, sum1, o);
    }
    if (lane == 0) { red_s[0][jq] = sum0; red_s[1][jq] = sum1; }
    __syncthreads();
    {
        float t0 = 0.f, t1 = 0.f;
        #pragma unroll
        for (int w = 0; w < 8; w++) { t0 += red_s[0][w]; t1 += red_s[1][w]; }
        sum0 = 1.f / t0; sum1 = 1.f / t1;
    }

    // write attn (own j-slice, both rows) to smem + global
    {
        int jp = jq * 32 + lane;
        float2 a0 = make_float2(s[0][0] * sum0, s[0][1] * sum0);
        float2 a1 = make_float2(s[1][0] * sum1, s[1][1] * sum1);
        ((float2*)attn_s[0])[jp] = a0;
        ((float2*)attn_s[1])[jp] = a1;
        float2* aout = (float2*)(out + (size_t)NB * L * DD + (size_t)row0 * L);
        aout[jp]          = a0;
        aout[L / 2 + jp]  = a1;
    }
    __syncthreads();

    // ---- attn @ vp over own j-slice; vv reused for both rows
    float ox0 = 0.f, oy0 = 0.f, ox1 = 0.f, oy1 = 0.f;
    const float2* vp2 = (const float2*)(g_vp + (size_t)b * L * DD);
    #pragma unroll 4
    for (int jj = 0; jj < 64; jj++) {
        int j = jq * 64 + jj;
        float2 vv = __ldg(vp2 + j * 32 + lane);
        float a0 = attn_s[0][j];
        float a1 = attn_s[1][j];
        ox0 += a0 * vv.x; oy0 += a0 * vv.y;
        ox1 += a1 * vv.x; oy1 += a1 * vv.y;
    }
    o_part[0][jq][2 * lane]     = ox0;
    o_part[0][jq][2 * lane + 1] = oy0;
    o_part[1][jq][2 * lane]     = ox1;
    o_part[1][jq][2 * lane + 1] = oy1;
    __syncthreads();

    // ---- warps 0,1 reduce partials + output projection (warp w -> row w)
    if (warp < 2) {
        int r  = warp;
        int d0 = 2 * lane;
        float fox = 0.f, foy = 0.f;
        #pragma unroll
        for (int w = 0; w < 8; w++) {
            fox += o_part[r][w][d0];
            foy += o_part[r][w][d0 + 1];
        }
        o_part[r][0][d0]     = fox;
        o_part[r][0][d0 + 1] = foy;
        __syncwarp();

        float f0 = db[d0], f1 = db[d0 + 1];
        const float2* Wd2 = (const float2*)Wd;
        #pragma unroll 8
        for (int e = 0; e < DD; e++) {
            float ov = o_part[r][0][e];
            float2 wv = __ldg(Wd2 + e * 32 + lane);
            f0 += ov * wv.x;
            f1 += ov * wv.y;
        }
        out[(row0 + r) * DD + d0]     = f0;
        out[(row0 + r) * DD + d0 + 1] = f1;
    }
}

// ---------------------------------------------------------------------------
// Inputs (metadata order): q, k, v, mask, Ww, wb, Wd, db, W1, b1, W2, b2
// Output: [out (B,H,LQ,D) | attn (B,H,LQ,LK)] as float32
// ---------------------------------------------------------------------------
extern "C" void kernel_launch(void* const* d_in, const int* in_sizes, int n_in,
                              void* d_out, int out_size)
{
    const float* q    = (const float*)d_in[0];
    const float* k    = (const float*)d_in[1];
    const float* v    = (const float*)d_in[2];
    const float* mask = (const float*)d_in[3];
    const float* Ww   = (const float*)d_in[4];
    const float* wb   = (const float*)d_in[5];
    const float* Wd   = (const float*)d_in[6];
    const float* db   = (const float*)d_in[7];
    const float* W1   = (const float*)d_in[8];
    const float* b1   = (const float*)d_in[9];
    const float* W2   = (const float*)d_in[10];
    const float* b2   = (const float*)d_in[11];
    float* out = (float*)d_out;

    prep_kernel<<<NB * (L / 4), 256>>>(q, k, v, Ww, wb, W1, b1);
    attn_kernel<<<NB * (L / 2), 256>>>(mask, Wd, db, W2, b2, out);
}

// round 10
// speedup vs baseline: 1.2249x; 1.2249x over previous
#include <cuda_runtime.h>
#include <cuda_bf16.h>

// Problem constants: B=2, H=1, LQ=LK=512, D=64, HID=128
#define NB   2
#define L    512
#define DD   64
#define HID  128

// Scratch (allocation-free rule: __device__ globals)
__device__ float  g_vp[NB * L * DD];             // projected V
__device__ float  g_qaqb[NB * L * HID * 2];      // interleaved (qa, qb) per (row, h)
__device__ float2 g_kbkaT[NB * HID * L];         // TRANSPOSED: [b][h][j] -> (kb+b1, ka+b1)

// ---------------------------------------------------------------------------
// Kernel A: projections + pairwise-MLP feature precompute. (unchanged)
// ---------------------------------------------------------------------------
__global__ __launch_bounds__(256) void prep_kernel(
    const float* __restrict__ q, const float* __restrict__ k,
    const float* __restrict__ v, const float* __restrict__ Ww,
    const float* __restrict__ wb, const float* __restrict__ W1,
    const float* __restrict__ b1)
{
    __shared__ float q_s[4][DD], k_s[4][DD], v_s[4][DD];
    __shared__ float qp_s[4][DD], kp_s[4][DD];

    const int tid  = threadIdx.x;
    const int b    = blockIdx.x >> 7;
    const int r0   = (blockIdx.x & 127) * 4;
    const int base = (b * L + r0) * DD;

    {
        int r = tid >> 6, e = tid & 63;
        q_s[r][e] = q[base + tid];
        k_s[r][e] = k[base + tid];
        v_s[r][e] = v[base + tid];
    }
    __syncthreads();

    {
        int pj = tid >> 6, d = tid & 63;
        if (pj < 3) {
            const float (*src)[DD] = (pj == 0) ? q_s : (pj == 1) ? k_s : v_s;
            float acc[4];
            float bias = wb[d];
            #pragma unroll
            for (int r = 0; r < 4; r++) acc[r] = bias;
            #pragma unroll 8
            for (int e = 0; e < DD; e++) {
                float w = Ww[e * DD + d];
                #pragma unroll
                for (int r = 0; r < 4; r++) acc[r] += src[r][e] * w;
            }
            #pragma unroll
            for (int r = 0; r < 4; r++) {
                if (pj == 0)      qp_s[r][d] = acc[r];
                else if (pj == 1) kp_s[r][d] = acc[r];
                else              g_vp[base + r * DD + d] = acc[r];
            }
        }
    }
    __syncthreads();

    {
        int half = tid >> 7;
        int h    = tid & 127;
        const float (*src)[DD] = half ? kp_s : qp_s;
        float accA[4] = {0.f, 0.f, 0.f, 0.f};
        float accB[4] = {0.f, 0.f, 0.f, 0.f};
        #pragma unroll 8
        for (int e = 0; e < DD; e++) {
            float w1q = W1[e * HID + h];
            float w1k = W1[(DD + e) * HID + h];
            #pragma unroll
            for (int r = 0; r < 4; r++) {
                float x = src[r][e];
                accA[r] += x * w1q;
                accB[r] += x * w1k;
            }
        }
        float bb = b1[h];
        #pragma unroll
        for (int r = 0; r < 4; r++) {
            if (!half) {
                int off = ((b * L + r0 + r) * HID + h) * 2;
                g_qaqb[off + 0] = accA[r];
                g_qaqb[off + 1] = accB[r];
            } else {
                g_kbkaT[(b * HID + h) * L + (r0 + r)] =
                    make_float2(accB[r] + bb, accA[r] + bb);
            }
        }
    }
}

// ---------------------------------------------------------------------------
// Kernel B: grid = NB*(L/2) = 512 blocks, 512 threads = 16 warps.
// Block covers 2 i-rows. Warp (jh, jq): jh = h-half (64 h), jq = j-slice of 64.
// Lane owns one j-pair: one LDG.128 of kk per h feeds 4 (row,j) scores.
// Scalar FADD/FMNMX/FFMA math (proven fastest); h-halves combined in smem.
// ---------------------------------------------------------------------------
__global__ __launch_bounds__(512, 2) void attn_kernel(
    const float* __restrict__ mask, const float* __restrict__ Wd,
    const float* __restrict__ db,   const float* __restrict__ W2,
    const float* __restrict__ b2,   float* __restrict__ out)
{
    __shared__ float4 qq_s[HID];         // (qa0,qb0,qa1,qb1) per h
    __shared__ float  w2_s[HID];
    __shared__ float  attn_s[2][L];
    __shared__ float  sp[8][32][4];      // jh=1 partial scores [jq][lane][4]
    __shared__ float  red_m[2][8], red_s[2][8];
    __shared__ float  o_part[2][16][DD];

    const int tid   = threadIdx.x;
    const int warp  = tid >> 5;
    const int lane  = tid & 31;
    const int jq    = warp & 7;          // j-slice
    const int jh    = warp >> 3;         // h-half
    const int b     = blockIdx.x >> 8;   // / 256
    const int itile = blockIdx.x & 255;
    const int row0  = b * L + itile * 2;

    // Stage packed q-features + W2
    if (tid < HID) {
        const float2* q0 = (const float2*)(g_qaqb + (size_t)row0 * (HID * 2));
        float2 a0 = q0[tid];
        float2 a1 = q0[HID + tid];
        qq_s[tid] = make_float4(a0.x, a0.y, a1.x, a1.y);
    } else if (tid < 2 * HID) {
        w2_s[tid - HID] = W2[tid - HID];
    }
    __syncthreads();

    // ---- scores over own h-half
    const float4* kt = reinterpret_cast<const float4*>(
        g_kbkaT + (size_t)(b * HID + jh * 64) * L) + jq * 32 + lane;

    float a00 = 0.f, a01 = 0.f, a10 = 0.f, a11 = 0.f;  // [row][j]

    #pragma unroll 4
    for (int hh = 0; hh < 64; hh++) {
        float4 kk = __ldg(kt + hh * (L / 2));   // (kb_j0, ka_j0, kb_j1, ka_j1)
        float4 qv = qq_s[jh * 64 + hh];         // (qa0, qb0, qa1, qb1)
        float  w2 = w2_s[jh * 64 + hh];
        a00 += (fmaxf(qv.x + kk.x, 0.f) + fmaxf(qv.y + kk.y, 0.f)) * w2;
        a01 += (fmaxf(qv.x + kk.z, 0.f) + fmaxf(qv.y + kk.w, 0.f)) * w2;
        a10 += (fmaxf(qv.z + kk.x, 0.f) + fmaxf(qv.w + kk.y, 0.f)) * w2;
        a11 += (fmaxf(qv.z + kk.z, 0.f) + fmaxf(qv.w + kk.w, 0.f)) * w2;
    }

    // combine h-halves: jh=1 dumps partials, jh=0 accumulates
    if (jh == 1) {
        sp[jq][lane][0] = a00;
        sp[jq][lane][1] = a01;
        sp[jq][lane][2] = a10;
        sp[jq][lane][3] = a11;
    }
    __syncthreads();

    float s00, s01, s10, s11;
    float m0 = -1e30f, m1 = -1e30f;
    if (jh == 0) {
        const float b2v2 = 2.f * b2[0];
        const float2* mrow = (const float2*)(mask + (size_t)row0 * L) + jq * 32 + lane;
        float2 mm0 = __ldg(mrow);
        float2 mm1 = __ldg(mrow + L / 2);
        s00 = a00 + sp[jq][lane][0] + b2v2 + mm0.x * (-1e9f);
        s01 = a01 + sp[jq][lane][1] + b2v2 + mm0.y * (-1e9f);
        s10 = a10 + sp[jq][lane][2] + b2v2 + mm1.x * (-1e9f);
        s11 = a11 + sp[jq][lane][3] + b2v2 + mm1.y * (-1e9f);

        m0 = fmaxf(s00, s01);
        m1 = fmaxf(s10, s11);
        #pragma unroll
        for (int o = 16; o > 0; o >>= 1) {
            m0 = fmaxf(m0, __shfl_xor_sync(0xffffffffu, m0, o));
            m1 = fmaxf(m1, __shfl_xor_sync(0xffffffffu, m1, o));
        }
        if (lane == 0) { red_m[0][jq] = m0; red_m[1][jq] = m1; }
    }
    __syncthreads();

    if (jh == 0) {
        float g0 = red_m[0][0], g1 = red_m[1][0];
        #pragma unroll
        for (int w = 1; w < 8; w++) { g0 = fmaxf(g0, red_m[0][w]); g1 = fmaxf(g1, red_m[1][w]); }

        s00 = __expf(s00 - g0);
        s01 = __expf(s01 - g0);
        s10 = __expf(s10 - g1);
        s11 = __expf(s11 - g1);
        float sum0 = s00 + s01;
        float sum1 = s10 + s11;
        #pragma unroll
        for (int o = 16; o > 0; o >>= 1) {
            sum0 += __shfl_xor_sync(0xffffffffu, sum0, o);
            sum1 += __shfl_xor_sync(0xffffffffu, sum1, o);
        }
        if (lane == 0) { red_s[0][jq] = sum0; red_s[1][jq] = sum1; }
    }
    __syncthreads();

    if (jh == 0) {
        float t0 = 0.f, t1 = 0.f;
        #pragma unroll
        for (int w = 0; w < 8; w++) { t0 += red_s[0][w]; t1 += red_s[1][w]; }
        float inv0 = 1.f / t0, inv1 = 1.f / t1;

        int jp = jq * 32 + lane;
        float2 a0 = make_float2(s00 * inv0, s01 * inv0);
        float2 a1 = make_float2(s10 * inv1, s11 * inv1);
        ((float2*)attn_s[0])[jp] = a0;
        ((float2*)attn_s[1])[jp] = a1;
        float2* aout = (float2*)(out + (size_t)NB * L * DD + (size_t)row0 * L);
        aout[jp]          = a0;
        aout[L / 2 + jp]  = a1;
    }
    __syncthreads();

    // ---- attn @ vp: each of 16 warps covers 32 j; vv reused for both rows
    float ox0 = 0.f, oy0 = 0.f, ox1 = 0.f, oy1 = 0.f;
    const float2* vp2 = (const float2*)(g_vp + (size_t)b * L * DD);
    #pragma unroll 4
    for (int jj = 0; jj < 32; jj++) {
        int j = warp * 32 + jj;
        float2 vv = __ldg(vp2 + j * 32 + lane);
        float a0 = attn_s[0][j];
        float a1 = attn_s[1][j];
        ox0 += a0 * vv.x; oy0 += a0 * vv.y;
        ox1 += a1 * vv.x; oy1 += a1 * vv.y;
    }
    o_part[0][warp][2 * lane]     = ox0;
    o_part[0][warp][2 * lane + 1] = oy0;
    o_part[1][warp][2 * lane]     = ox1;
    o_part[1][warp][2 * lane + 1] = oy1;
    __syncthreads();

    // ---- warps 0,1 reduce partials + output projection (warp w -> row w)
    if (warp < 2) {
        int r  = warp;
        int d0 = 2 * lane;
        float fox = 0.f, foy = 0.f;
        #pragma unroll
        for (int w = 0; w < 16; w++) {
            fox += o_part[r][w][d0];
            foy += o_part[r][w][d0 + 1];
        }
        o_part[r][0][d0]     = fox;
        o_part[r][0][d0 + 1] = foy;
        __syncwarp();

        float f0 = db[d0], f1 = db[d0 + 1];
        const float2* Wd2 = (const float2*)Wd;
        #pragma unroll 8
        for (int e = 0; e < DD; e++) {
            float ov = o_part[r][0][e];
            float2 wv = __ldg(Wd2 + e * 32 + lane);
            f0 += ov * wv.x;
            f1 += ov * wv.y;
        }
        out[(row0 + r) * DD + d0]     = f0;
        out[(row0 + r) * DD + d0 + 1] = f1;
    }
}

// ---------------------------------------------------------------------------
// Inputs (metadata order): q, k, v, mask, Ww, wb, Wd, db, W1, b1, W2, b2
// Output: [out (B,H,LQ,D) | attn (B,H,LQ,LK)] as float32
// ---------------------------------------------------------------------------
extern "C" void kernel_launch(void* const* d_in, const int* in_sizes, int n_in,
                              void* d_out, int out_size)
{
    const float* q    = (const float*)d_in[0];
    const float* k    = (const float*)d_in[1];
    const float* v    = (const float*)d_in[2];
    const float* mask = (const float*)d_in[3];
    const float* Ww   = (const float*)d_in[4];
    const float* wb   = (const float*)d_in[5];
    const float* Wd   = (const float*)d_in[6];
    const float* db   = (const float*)d_in[7];
    const float* W1   = (const float*)d_in[8];
    const float* b1   = (const float*)d_in[9];
    const float* W2   = (const float*)d_in[10];
    const float* b2   = (const float*)d_in[11];
    float* out = (float*)d_out;

    prep_kernel<<<NB * (L / 4), 256>>>(q, k, v, Ww, wb, W1, b1);
    attn_kernel<<<NB * (L / 2), 512>>>(mask, Wd, db, W2, b2, out);
}

// round 11
// speedup vs baseline: 1.2732x; 1.0394x over previous
#include <cuda_runtime.h>
#include <cuda_bf16.h>

// Problem constants: B=2, H=1, LQ=LK=512, D=64, HID=128
#define NB   2
#define L    512
#define DD   64
#define HID  128

// Scratch (allocation-free rule: __device__ globals)
__device__ float  g_vp[NB * L * DD];             // projected V
__device__ float  g_qaqb[NB * L * HID * 2];      // interleaved (qa, qb) per (row, h)
__device__ float2 g_kbkaT[NB * HID * L];         // TRANSPOSED: [b][h][j] -> (kb+b1, ka+b1)
__device__ float  g_Cq[NB * L];                  // Σ_h (qa+qb)·w2/2 per q-row
__device__ float  g_Ck[NB * L];                  // Σ_h (kb'+ka')·w2/2 per k-row

// ---------------------------------------------------------------------------
// Kernel A: projections + pairwise-MLP feature precompute + rank-1 terms.
// grid = NB * (L/4) = 256 blocks, 256 threads.
// ---------------------------------------------------------------------------
__global__ __launch_bounds__(256) void prep_kernel(
    const float* __restrict__ q, const float* __restrict__ k,
    const float* __restrict__ v, const float* __restrict__ Ww,
    const float* __restrict__ wb, const float* __restrict__ W1,
    const float* __restrict__ b1, const float* __restrict__ W2)
{
    __shared__ float q_s[4][DD], k_s[4][DD], v_s[4][DD];
    __shared__ float qp_s[4][DD], kp_s[4][DD];
    __shared__ float red_c[8][4];        // per-warp partial rank-1 sums

    const int tid  = threadIdx.x;
    const int b    = blockIdx.x >> 7;
    const int r0   = (blockIdx.x & 127) * 4;
    const int base = (b * L + r0) * DD;

    {
        int r = tid >> 6, e = tid & 63;
        q_s[r][e] = q[base + tid];
        k_s[r][e] = k[base + tid];
        v_s[r][e] = v[base + tid];
    }
    __syncthreads();

    {
        int pj = tid >> 6, d = tid & 63;
        if (pj < 3) {
            const float (*src)[DD] = (pj == 0) ? q_s : (pj == 1) ? k_s : v_s;
            float acc[4];
            float bias = wb[d];
            #pragma unroll
            for (int r = 0; r < 4; r++) acc[r] = bias;
            #pragma unroll 8
            for (int e = 0; e < DD; e++) {
                float w = Ww[e * DD + d];
                #pragma unroll
                for (int r = 0; r < 4; r++) acc[r] += src[r][e] * w;
            }
            #pragma unroll
            for (int r = 0; r < 4; r++) {
                if (pj == 0)      qp_s[r][d] = acc[r];
                else if (pj == 1) kp_s[r][d] = acc[r];
                else              g_vp[base + r * DD + d] = acc[r];
            }
        }
    }
    __syncthreads();

    {
        int half = tid >> 7;     // 0: q-features, 1: k-features
        int h    = tid & 127;
        const float (*src)[DD] = half ? kp_s : qp_s;
        float accA[4] = {0.f, 0.f, 0.f, 0.f};   // · W1q
        float accB[4] = {0.f, 0.f, 0.f, 0.f};   // · W1k
        #pragma unroll 8
        for (int e = 0; e < DD; e++) {
            float w1q = W1[e * HID + h];
            float w1k = W1[(DD + e) * HID + h];
            #pragma unroll
            for (int r = 0; r < 4; r++) {
                float x = src[r][e];
                accA[r] += x * w1q;
                accB[r] += x * w1k;
            }
        }
        float bb = b1[h];
        float w2h = 0.5f * W2[h];
        float c[4];
        #pragma unroll
        for (int r = 0; r < 4; r++) {
            if (!half) {
                int off = ((b * L + r0 + r) * HID + h) * 2;
                g_qaqb[off + 0] = accA[r];                 // qa
                g_qaqb[off + 1] = accB[r];                 // qb
                c[r] = (accA[r] + accB[r]) * w2h;          // (qa+qb)·w2/2
            } else {
                float kb = accB[r] + bb, ka = accA[r] + bb;
                g_kbkaT[(b * HID + h) * L + (r0 + r)] = make_float2(kb, ka);
                c[r] = (kb + ka) * w2h;                    // (kb'+ka')·w2/2
            }
        }
        // block-reduce c over the 128 h of each half (4 warps per half)
        #pragma unroll
        for (int r = 0; r < 4; r++) {
            #pragma unroll
            for (int o = 16; o > 0; o >>= 1)
                c[r] += __shfl_xor_sync(0xffffffffu, c[r], o);
        }
        int warp = tid >> 5;
        if ((tid & 31) == 0) {
            #pragma unroll
            for (int r = 0; r < 4; r++) red_c[warp][r] = c[r];
        }
    }
    __syncthreads();

    if (tid < 8) {
        int half = tid >> 2, r = tid & 3;
        int w0 = half * 4;
        float s = red_c[w0][r] + red_c[w0 + 1][r] + red_c[w0 + 2][r] + red_c[w0 + 3][r];
        if (half == 0) g_Cq[b * L + r0 + r] = s;
        else           g_Ck[b * L + r0 + r] = s;
    }
}

// ---------------------------------------------------------------------------
// Kernel B: grid = NB*(L/2) = 512 blocks, 512 threads = 16 warps.
// Block covers 2 i-rows. Warp (jh, jq): jh = h-half (64 h), jq = j-slice of 64.
// Score loop uses relu(x) = (x+|x|)/2: rank-1 parts precomputed, pairwise part
// is FADD + FFMA(|t|, w2/2) only.
// ---------------------------------------------------------------------------
__global__ __launch_bounds__(512, 2) void attn_kernel(
    const float* __restrict__ mask, const float* __restrict__ Wd,
    const float* __restrict__ db,   const float* __restrict__ W2,
    const float* __restrict__ b2,   float* __restrict__ out)
{
    __shared__ float4 qq_s[HID];         // (qa0,qb0,qa1,qb1) per h
    __shared__ float  w2_s[HID];         // w2/2
    __shared__ float  attn_s[2][L];
    __shared__ float  sp[8][32][4];      // jh=1 partial scores [jq][lane][4]
    __shared__ float  red_m[2][8], red_s[2][8];
    __shared__ float  o_part[2][16][DD];

    const int tid   = threadIdx.x;
    const int warp  = tid >> 5;
    const int lane  = tid & 31;
    const int jq    = warp & 7;          // j-slice
    const int jh    = warp >> 3;         // h-half
    const int b     = blockIdx.x >> 8;   // / 256
    const int itile = blockIdx.x & 255;
    const int row0  = b * L + itile * 2;

    // Stage packed q-features + W2/2
    if (tid < HID) {
        const float2* q0 = (const float2*)(g_qaqb + (size_t)row0 * (HID * 2));
        float2 a0 = q0[tid];
        float2 a1 = q0[HID + tid];
        qq_s[tid] = make_float4(a0.x, a0.y, a1.x, a1.y);
    } else if (tid < 2 * HID) {
        w2_s[tid - HID] = 0.5f * W2[tid - HID];
    }
    __syncthreads();

    // ---- |.|-part of scores over own h-half
    const float4* kt = reinterpret_cast<const float4*>(
        g_kbkaT + (size_t)(b * HID + jh * 64) * L) + jq * 32 + lane;

    float a00 = 0.f, a01 = 0.f, a10 = 0.f, a11 = 0.f;  // [row][j]

    #pragma unroll 4
    for (int hh = 0; hh < 64; hh++) {
        float4 kk = __ldg(kt + hh * (L / 2));   // (kb_j0, ka_j0, kb_j1, ka_j1)
        float4 qv = qq_s[jh * 64 + hh];         // (qa0, qb0, qa1, qb1)
        float  wh = w2_s[jh * 64 + hh];
        a00 = fmaf(fabsf(qv.x + kk.x), wh, a00);
        a00 = fmaf(fabsf(qv.y + kk.y), wh, a00);
        a01 = fmaf(fabsf(qv.x + kk.z), wh, a01);
        a01 = fmaf(fabsf(qv.y + kk.w), wh, a01);
        a10 = fmaf(fabsf(qv.z + kk.x), wh, a10);
        a10 = fmaf(fabsf(qv.w + kk.y), wh, a10);
        a11 = fmaf(fabsf(qv.z + kk.z), wh, a11);
        a11 = fmaf(fabsf(qv.w + kk.w), wh, a11);
    }

    // combine h-halves: jh=1 dumps partials, jh=0 accumulates
    if (jh == 1) {
        sp[jq][lane][0] = a00;
        sp[jq][lane][1] = a01;
        sp[jq][lane][2] = a10;
        sp[jq][lane][3] = a11;
    }
    __syncthreads();

    float s00, s01, s10, s11;
    if (jh == 0) {
        const float b2v2 = 2.f * b2[0];
        const float cq0 = g_Cq[row0], cq1 = g_Cq[row0 + 1];
        int jp = jq * 32 + lane;
        float2 ckv = ((const float2*)(g_Ck + (size_t)b * L))[jp];   // (Ck_j0, Ck_j1)
        const float2* mrow = (const float2*)(mask + (size_t)row0 * L) + jp;
        float2 mm0 = __ldg(mrow);
        float2 mm1 = __ldg(mrow + L / 2);
        s00 = a00 + sp[jq][lane][0] + cq0 + ckv.x + b2v2 + mm0.x * (-1e9f);
        s01 = a01 + sp[jq][lane][1] + cq0 + ckv.y + b2v2 + mm0.y * (-1e9f);
        s10 = a10 + sp[jq][lane][2] + cq1 + ckv.x + b2v2 + mm1.x * (-1e9f);
        s11 = a11 + sp[jq][lane][3] + cq1 + ckv.y + b2v2 + mm1.y * (-1e9f);

        float m0 = fmaxf(s00, s01);
        float m1 = fmaxf(s10, s11);
        #pragma unroll
        for (int o = 16; o > 0; o >>= 1) {
            m0 = fmaxf(m0, __shfl_xor_sync(0xffffffffu, m0, o));
            m1 = fmaxf(m1, __shfl_xor_sync(0xffffffffu, m1, o));
        }
        if (lane == 0) { red_m[0][jq] = m0; red_m[1][jq] = m1; }
    }
    __syncthreads();

    if (jh == 0) {
        float g0 = red_m[0][0], g1 = red_m[1][0];
        #pragma unroll
        for (int w = 1; w < 8; w++) { g0 = fmaxf(g0, red_m[0][w]); g1 = fmaxf(g1, red_m[1][w]); }

        s00 = __expf(s00 - g0);
        s01 = __expf(s01 - g0);
        s10 = __expf(s10 - g1);
        s11 = __expf(s11 - g1);
        float sum0 = s00 + s01;
        float sum1 = s10 + s11;
        #pragma unroll
        for (int o = 16; o > 0; o >>= 1) {
            sum0 += __shfl_xor_sync(0xffffffffu, sum0, o);
            sum1 += __shfl_xor_sync(0xffffffffu, sum1, o);
        }
        if (lane == 0) { red_s[0][jq] = sum0; red_s[1][jq] = sum1; }
    }
    __syncthreads();

    if (jh == 0) {
        float t0 = 0.f, t1 = 0.f;
        #pragma unroll
        for (int w = 0; w < 8; w++) { t0 += red_s[0][w]; t1 += red_s[1][w]; }
        float inv0 = 1.f / t0, inv1 = 1.f / t1;

        int jp = jq * 32 + lane;
        float2 a0 = make_float2(s00 * inv0, s01 * inv0);
        float2 a1 = make_float2(s10 * inv1, s11 * inv1);
        ((float2*)attn_s[0])[jp] = a0;
        ((float2*)attn_s[1])[jp] = a1;
        float2* aout = (float2*)(out + (size_t)NB * L * DD + (size_t)row0 * L);
        aout[jp]          = a0;
        aout[L / 2 + jp]  = a1;
    }
    __syncthreads();

    // ---- attn @ vp: each of 16 warps covers 32 j; vv reused for both rows
    float ox0 = 0.f, oy0 = 0.f, ox1 = 0.f, oy1 = 0.f;
    const float2* vp2 = (const float2*)(g_vp + (size_t)b * L * DD);
    #pragma unroll 4
    for (int jj = 0; jj < 32; jj++) {
        int j = warp * 32 + jj;
        float2 vv = __ldg(vp2 + j * 32 + lane);
        float a0 = attn_s[0][j];
        float a1 = attn_s[1][j];
        ox0 += a0 * vv.x; oy0 += a0 * vv.y;
        ox1 += a1 * vv.x; oy1 += a1 * vv.y;
    }
    o_part[0][warp][2 * lane]     = ox0;
    o_part[0][warp][2 * lane + 1] = oy0;
    o_part[1][warp][2 * lane]     = ox1;
    o_part[1][warp][2 * lane + 1] = oy1;
    __syncthreads();

    // ---- warps 0,1 reduce partials + output projection (warp w -> row w)
    if (warp < 2) {
        int r  = warp;
        int d0 = 2 * lane;
        float fox = 0.f, foy = 0.f;
        #pragma unroll
        for (int w = 0; w < 16; w++) {
            fox += o_part[r][w][d0];
            foy += o_part[r][w][d0 + 1];
        }
        o_part[r][0][d0]     = fox;
        o_part[r][0][d0 + 1] = foy;
        __syncwarp();

        float f0 = db[d0], f1 = db[d0 + 1];
        const float2* Wd2 = (const float2*)Wd;
        #pragma unroll 8
        for (int e = 0; e < DD; e++) {
            float ov = o_part[r][0][e];
            float2 wv = __ldg(Wd2 + e * 32 + lane);
            f0 += ov * wv.x;
            f1 += ov * wv.y;
        }
        out[(row0 + r) * DD + d0]     = f0;
        out[(row0 + r) * DD + d0 + 1] = f1;
    }
}

// ---------------------------------------------------------------------------
// Inputs (metadata order): q, k, v, mask, Ww, wb, Wd, db, W1, b1, W2, b2
// Output: [out (B,H,LQ,D) | attn (B,H,LQ,LK)] as float32
// ---------------------------------------------------------------------------
extern "C" void kernel_launch(void* const* d_in, const int* in_sizes, int n_in,
                              void* d_out, int out_size)
{
    const float* q    = (const float*)d_in[0];
    const float* k    = (const float*)d_in[1];
    const float* v    = (const float*)d_in[2];
    const float* mask = (const float*)d_in[3];
    const float* Ww   = (const float*)d_in[4];
    const float* wb   = (const float*)d_in[5];
    const float* Wd   = (const float*)d_in[6];
    const float* db   = (const float*)d_in[7];
    const float* W1   = (const float*)d_in[8];
    const float* b1   = (const float*)d_in[9];
    const float* W2   = (const float*)d_in[10];
    const float* b2   = (const float*)d_in[11];
    float* out = (float*)d_out;

    prep_kernel<<<NB * (L / 4), 256>>>(q, k, v, Ww, wb, W1, b1, W2);
    attn_kernel<<<NB * (L / 2), 512>>>(mask, Wd, db, W2, b2, out);
}